// round 1
// baseline (speedup 1.0000x reference)
#include <cuda_runtime.h>
#include <cuda_bf16.h>
#include <math.h>

#define D_MODEL 1024
#define NUM_HEADS 16
#define SEQ 2048
#define BATCH 4
#define D_K 64
#define MTOT (BATCH * SEQ)   // 8192

// Scratch (static device globals; no runtime allocation allowed)
__device__ float g_q[MTOT * D_MODEL];
__device__ float g_k[MTOT * D_MODEL];
__device__ float g_v[MTOT * D_MODEL];
__device__ float g_o[MTOT * D_MODEL];

// ---------------------------------------------------------------------------
// Tiled SGEMM, NT form:  C[m,n] = sum_k A[m,k] * B[n,k]
// A: [M,K] row-major, B: [N,K] row-major (i.e. weight W so C = A @ W^T)
// BM=BN=128, BK=8, 256 threads, 8x8 micro-tile per thread.
// rope != 0: apply RoPE to pairs (even,odd) within each 64-wide head slice.
// ---------------------------------------------------------------------------
__global__ __launch_bounds__(256, 2)
void sgemm_nt(const float* __restrict__ A, const float* __restrict__ B,
              float* __restrict__ C, int M, int N, int K,
              int rope, const int* __restrict__ pos)
{
    __shared__ float As[8][132];
    __shared__ float Bs[8][132];

    const int tid = threadIdx.x;
    const int tx = tid & 15;          // 0..15  -> col group
    const int ty = tid >> 4;          // 0..15  -> row group
    const int bm = blockIdx.y * 128;
    const int bn = blockIdx.x * 128;

    const int lrow = tid >> 1;        // 0..127
    const int lcol = (tid & 1) * 4;   // 0 or 4

    float acc[8][8];
#pragma unroll
    for (int i = 0; i < 8; i++)
#pragma unroll
        for (int j = 0; j < 8; j++) acc[i][j] = 0.0f;

    const int ktiles = K >> 3;
    for (int kt = 0; kt < ktiles; kt++) {
        // load A tile 128x8 (transposed into smem), B tile 128x8
        float4 a4 = *(const float4*)&A[(size_t)(bm + lrow) * K + kt * 8 + lcol];
        float4 b4 = *(const float4*)&B[(size_t)(bn + lrow) * K + kt * 8 + lcol];
        As[lcol + 0][lrow] = a4.x; As[lcol + 1][lrow] = a4.y;
        As[lcol + 2][lrow] = a4.z; As[lcol + 3][lrow] = a4.w;
        Bs[lcol + 0][lrow] = b4.x; Bs[lcol + 1][lrow] = b4.y;
        Bs[lcol + 2][lrow] = b4.z; Bs[lcol + 3][lrow] = b4.w;
        __syncthreads();

#pragma unroll
        for (int k = 0; k < 8; k++) {
            float4 ra0 = *(const float4*)&As[k][ty * 8];
            float4 ra1 = *(const float4*)&As[k][ty * 8 + 4];
            float4 rb0 = *(const float4*)&Bs[k][tx * 8];
            float4 rb1 = *(const float4*)&Bs[k][tx * 8 + 4];
            float ar[8] = {ra0.x, ra0.y, ra0.z, ra0.w, ra1.x, ra1.y, ra1.z, ra1.w};
            float br[8] = {rb0.x, rb0.y, rb0.z, rb0.w, rb1.x, rb1.y, rb1.z, rb1.w};
#pragma unroll
            for (int i = 0; i < 8; i++)
#pragma unroll
                for (int j = 0; j < 8; j++) acc[i][j] = fmaf(ar[i], br[j], acc[i][j]);
        }
        __syncthreads();
    }

    // epilogue
    const int m0 = bm + ty * 8;
    const int n0 = bn + tx * 8;
    if (rope) {
        const float lg = logf(10000.0f);
#pragma unroll
        for (int i = 0; i < 8; i++) {
            int m = m0 + i;
            float p = (float)pos[m & (SEQ - 1)];
#pragma unroll
            for (int j = 0; j < 8; j += 2) {
                int n = n0 + j;
                int d = n & (D_K - 1);              // even
                float invf = expf(-lg * ((float)d / (float)D_K));
                float ang = p * invf;
                float sn, cs;
                sincosf(ang, &sn, &cs);
                float v0 = acc[i][j], v1 = acc[i][j + 1];
                C[(size_t)m * N + n]     = v0 * cs - v1 * sn;
                C[(size_t)m * N + n + 1] = v0 * sn + v1 * cs;
            }
        }
    } else {
#pragma unroll
        for (int i = 0; i < 8; i++) {
            int m = m0 + i;
#pragma unroll
            for (int j = 0; j < 8; j += 4) {
                float4 v = make_float4(acc[i][j], acc[i][j+1], acc[i][j+2], acc[i][j+3]);
                *(float4*)&C[(size_t)m * N + n0 + j] = v;
            }
        }
    }
}

// ---------------------------------------------------------------------------
// Flash attention (fp32, causal). Br=64 queries, Bc=32 keys per iteration.
// grid: (32 q-tiles, 64 b*h). block: 256 threads. O accumulator in registers.
// Q/K/V are in [B*S, D_MODEL] layout; head h = cols [h*64, h*64+64).
// ---------------------------------------------------------------------------
__global__ __launch_bounds__(256, 2)
void attn_kernel(const float* __restrict__ Qg, const float* __restrict__ Kg,
                 const float* __restrict__ Vg, float* __restrict__ Og)
{
    __shared__ float Qs[64][68];
    __shared__ float Ks[32][68];
    __shared__ float Vs[32][68];
    __shared__ float Ss[64][36];
    __shared__ float m_s[64], l_s[64], a_s[64];

    const int tid = threadIdx.x;
    const int qt = blockIdx.x;
    const int bh = blockIdx.y;
    const int b = bh >> 4;
    const int h = bh & 15;
    const int q0 = qt * 64;
    const float scale = 0.125f;   // 1/sqrt(64)

    const size_t base = (size_t)b * SEQ * D_MODEL + (size_t)h * D_K;

    // load Q tile (64 x 64)
#pragma unroll
    for (int i = 0; i < 4; i++) {
        int e = tid + i * 256;            // 0..1023
        int r = e >> 4;
        int c = (e & 15) * 4;
        *(float4*)&Qs[r][c] = *(const float4*)&Qg[base + (size_t)(q0 + r) * D_MODEL + c];
    }
    if (tid < 64) { m_s[tid] = -1e30f; l_s[tid] = 0.0f; }

    // PV-phase thread mapping (also used for O accumulator)
    const int pc0 = (tid & 15) * 4;       // col  0..60
    const int pr0 = (tid >> 4) * 4;       // row  0..60
    float o[4][4];
#pragma unroll
    for (int i = 0; i < 4; i++)
#pragma unroll
        for (int j = 0; j < 4; j++) o[i][j] = 0.0f;

    // S-phase thread mapping
    const int sc0 = (tid & 7) * 4;        // col 0..28
    const int sr0 = (tid >> 3) * 2;       // row 0..62

    const int nkb = 2 * qt + 2;           // causal: keys up to q0+63
    __syncthreads();

    for (int kb = 0; kb < nkb; kb++) {
        const int k0 = kb * 32;
        // load K,V tiles (32 x 64)
#pragma unroll
        for (int i = 0; i < 2; i++) {
            int e = tid + i * 256;        // 0..511
            int r = e >> 4;
            int c = (e & 15) * 4;
            *(float4*)&Ks[r][c] = *(const float4*)&Kg[base + (size_t)(k0 + r) * D_MODEL + c];
            *(float4*)&Vs[r][c] = *(const float4*)&Vg[base + (size_t)(k0 + r) * D_MODEL + c];
        }
        __syncthreads();

        // S = Q K^T * scale  (64 x 32), 2x4 per thread
        {
            float acc[2][4] = {{0,0,0,0},{0,0,0,0}};
            const float4* qr0 = (const float4*)&Qs[sr0][0];
            const float4* qr1 = (const float4*)&Qs[sr0 + 1][0];
#pragma unroll
            for (int k4 = 0; k4 < 16; k4++) {
                float4 a0 = qr0[k4];
                float4 a1 = qr1[k4];
#pragma unroll
                for (int j = 0; j < 4; j++) {
                    float4 kk = *(const float4*)&Ks[sc0 + j][k4 * 4];
                    acc[0][j] += a0.x*kk.x + a0.y*kk.y + a0.z*kk.z + a0.w*kk.w;
                    acc[1][j] += a1.x*kk.x + a1.y*kk.y + a1.z*kk.z + a1.w*kk.w;
                }
            }
#pragma unroll
            for (int i = 0; i < 2; i++)
#pragma unroll
                for (int j = 0; j < 4; j++) {
                    int qg = q0 + sr0 + i;
                    int kg = k0 + sc0 + j;
                    Ss[sr0 + i][sc0 + j] = (kg <= qg) ? acc[i][j] * scale : -1e30f;
                }
        }
        __syncthreads();

        // online softmax per row (threads 0..63)
        if (tid < 64) {
            float mold = m_s[tid];
            float mx = mold;
#pragma unroll 8
            for (int c = 0; c < 32; c++) mx = fmaxf(mx, Ss[tid][c]);
            float al = __expf(mold - mx);
            float sum = 0.0f;
#pragma unroll 8
            for (int c = 0; c < 32; c++) {
                float p = __expf(Ss[tid][c] - mx);
                Ss[tid][c] = p;
                sum += p;
            }
            l_s[tid] = l_s[tid] * al + sum;
            m_s[tid] = mx;
            a_s[tid] = al;
        }
        __syncthreads();

        // O = O*alpha + P @ V   (64 x 64), 4x4 per thread, inner = 32
        {
#pragma unroll
            for (int i = 0; i < 4; i++) {
                float al = a_s[pr0 + i];
#pragma unroll
                for (int j = 0; j < 4; j++) o[i][j] *= al;
            }
#pragma unroll
            for (int kk = 0; kk < 32; kk++) {
                float4 vv = *(const float4*)&Vs[kk][pc0];
#pragma unroll
                for (int i = 0; i < 4; i++) {
                    float p = Ss[pr0 + i][kk];
                    o[i][0] = fmaf(p, vv.x, o[i][0]);
                    o[i][1] = fmaf(p, vv.y, o[i][1]);
                    o[i][2] = fmaf(p, vv.z, o[i][2]);
                    o[i][3] = fmaf(p, vv.w, o[i][3]);
                }
            }
        }
        __syncthreads();   // protect Ks/Vs/Ss before next iteration's loads
    }

    // final normalize + write O to [B*S, D_MODEL]
#pragma unroll
    for (int i = 0; i < 4; i++) {
        int r = pr0 + i;
        float inv_l = 1.0f / l_s[r];
        float4 v = make_float4(o[i][0]*inv_l, o[i][1]*inv_l, o[i][2]*inv_l, o[i][3]*inv_l);
        *(float4*)&Og[base + (size_t)(q0 + r) * D_MODEL + pc0] = v;
    }
}

// ---------------------------------------------------------------------------
extern "C" void kernel_launch(void* const* d_in, const int* in_sizes, int n_in,
                              void* d_out, int out_size)
{
    const float* x  = (const float*)d_in[0];
    const float* wq = (const float*)d_in[1];
    const float* wk = (const float*)d_in[2];
    const float* wv = (const float*)d_in[3];
    const float* wo = (const float*)d_in[4];
    const int* tok  = (const int*)d_in[5];
    float* out = (float*)d_out;

    float *qp, *kp, *vp, *op;
    cudaGetSymbolAddress((void**)&qp, g_q);
    cudaGetSymbolAddress((void**)&kp, g_k);
    cudaGetSymbolAddress((void**)&vp, g_v);
    cudaGetSymbolAddress((void**)&op, g_o);

    dim3 gg(D_MODEL / 128, MTOT / 128);   // (8, 64)
    sgemm_nt<<<gg, 256>>>(x, wq, qp, MTOT, D_MODEL, D_MODEL, 1, tok);
    sgemm_nt<<<gg, 256>>>(x, wk, kp, MTOT, D_MODEL, D_MODEL, 1, tok);
    sgemm_nt<<<gg, 256>>>(x, wv, vp, MTOT, D_MODEL, D_MODEL, 0, nullptr);

    dim3 ga(SEQ / 64, BATCH * NUM_HEADS); // (32, 64)
    attn_kernel<<<ga, 256>>>(qp, kp, vp, op);

    sgemm_nt<<<gg, 256>>>(op, wo, out, MTOT, D_MODEL, D_MODEL, 0, nullptr);
}

// round 2
// speedup vs baseline: 3.0355x; 3.0355x over previous
#include <cuda_runtime.h>
#include <cuda_bf16.h>
#include <math.h>
#include <stdint.h>

#define D_MODEL 1024
#define NUM_HEADS 16
#define SEQ 2048
#define BATCH 4
#define D_K 64
#define MTOT (BATCH * SEQ)   // 8192

// Scratch (static device globals; no runtime allocation allowed)
__device__ float g_q[MTOT * D_MODEL];
__device__ float g_k[MTOT * D_MODEL];
__device__ float g_v[MTOT * D_MODEL];
__device__ float g_o[MTOT * D_MODEL];

// ---------------------------------------------------------------------------
// helpers
// ---------------------------------------------------------------------------
__device__ __forceinline__ uint32_t f2tf32(float f) {
    uint32_t r;
    asm("cvt.rna.tf32.f32 %0, %1;" : "=r"(r) : "f"(f));
    return r;
}

__device__ __forceinline__ void mma_tf32(float c[4], uint32_t a0, uint32_t a1,
                                         uint32_t a2, uint32_t a3,
                                         uint32_t b0, uint32_t b1) {
    asm volatile(
        "mma.sync.aligned.m16n8k8.row.col.f32.tf32.tf32.f32 "
        "{%0,%1,%2,%3},{%4,%5,%6,%7},{%8,%9},{%0,%1,%2,%3};"
        : "+f"(c[0]), "+f"(c[1]), "+f"(c[2]), "+f"(c[3])
        : "r"(a0), "r"(a1), "r"(a2), "r"(a3), "r"(b0), "r"(b1));
}

// ---------------------------------------------------------------------------
// tf32 tensor-core SGEMM, NT form: C[m,n] = sum_k A[m,k]*B[n,k]
// Block tile 128x128x32, 256 threads = 8 warps (2x4), warp tile 64x32.
// rope != 0: apply RoPE to (even,odd) pairs within each 64-wide head slice.
// ---------------------------------------------------------------------------
__global__ __launch_bounds__(256)
void gemm_tf32(const float* __restrict__ A, const float* __restrict__ B,
               float* __restrict__ C, int rope, const int* __restrict__ pos)
{
    // K-major smem, row stride 136 (136 mod 32 == 8 -> conflict-free frags)
    __shared__ float As[32][136];
    __shared__ float Bs[32][136];

    const int tid = threadIdx.x;
    const int warp = tid >> 5;
    const int lane = tid & 31;
    const int gid = lane >> 2;       // 0..7
    const int tig = lane & 3;        // 0..3
    const int warp_m = warp >> 2;    // 0..1
    const int warp_n = warp & 3;     // 0..3

    const int bm = blockIdx.y * 128;
    const int bn = blockIdx.x * 128;

    const int lrow = tid >> 1;               // 0..127
    const int lcsel = (tid & 1) * 4;         // 0 or 4

    float acc[4][4][4];
#pragma unroll
    for (int i = 0; i < 4; i++)
#pragma unroll
        for (int j = 0; j < 4; j++)
#pragma unroll
            for (int v = 0; v < 4; v++) acc[i][j][v] = 0.0f;

    const float* Arow = A + (size_t)(bm + lrow) * D_MODEL;
    const float* Brow = B + (size_t)(bn + lrow) * D_MODEL;

    float4 pa[4], pb[4];
#pragma unroll
    for (int kk = 0; kk < 4; kk++) {
        pa[kk] = *(const float4*)&Arow[lcsel + kk * 8];
        pb[kk] = *(const float4*)&Brow[lcsel + kk * 8];
    }

    const int NKT = D_MODEL / 32;   // 32
    for (int kt = 0; kt < NKT; kt++) {
#pragma unroll
        for (int kk = 0; kk < 4; kk++) {
            int c = lcsel + kk * 8;
            As[c + 0][lrow] = __uint_as_float(f2tf32(pa[kk].x));
            As[c + 1][lrow] = __uint_as_float(f2tf32(pa[kk].y));
            As[c + 2][lrow] = __uint_as_float(f2tf32(pa[kk].z));
            As[c + 3][lrow] = __uint_as_float(f2tf32(pa[kk].w));
            Bs[c + 0][lrow] = __uint_as_float(f2tf32(pb[kk].x));
            Bs[c + 1][lrow] = __uint_as_float(f2tf32(pb[kk].y));
            Bs[c + 2][lrow] = __uint_as_float(f2tf32(pb[kk].z));
            Bs[c + 3][lrow] = __uint_as_float(f2tf32(pb[kk].w));
        }
        __syncthreads();

        if (kt + 1 < NKT) {
            const float* An = Arow + (kt + 1) * 32;
            const float* Bn = Brow + (kt + 1) * 32;
#pragma unroll
            for (int kk = 0; kk < 4; kk++) {
                pa[kk] = *(const float4*)&An[lcsel + kk * 8];
                pb[kk] = *(const float4*)&Bn[lcsel + kk * 8];
            }
        }

#pragma unroll
        for (int ks = 0; ks < 32; ks += 8) {
            uint32_t af[4][4], bf[4][2];
#pragma unroll
            for (int mt = 0; mt < 4; mt++) {
                int r = warp_m * 64 + mt * 16 + gid;
                af[mt][0] = __float_as_uint(As[ks + tig][r]);
                af[mt][1] = __float_as_uint(As[ks + tig][r + 8]);
                af[mt][2] = __float_as_uint(As[ks + tig + 4][r]);
                af[mt][3] = __float_as_uint(As[ks + tig + 4][r + 8]);
            }
#pragma unroll
            for (int nt = 0; nt < 4; nt++) {
                int c = warp_n * 32 + nt * 8 + gid;
                bf[nt][0] = __float_as_uint(Bs[ks + tig][c]);
                bf[nt][1] = __float_as_uint(Bs[ks + tig + 4][c]);
            }
#pragma unroll
            for (int mt = 0; mt < 4; mt++)
#pragma unroll
                for (int nt = 0; nt < 4; nt++)
                    mma_tf32(acc[mt][nt], af[mt][0], af[mt][1], af[mt][2],
                             af[mt][3], bf[nt][0], bf[nt][1]);
        }
        __syncthreads();
    }

    if (rope) {
        const float lg = logf(10000.0f);
#pragma unroll
        for (int mt = 0; mt < 4; mt++) {
            int r0 = bm + warp_m * 64 + mt * 16 + gid;
            float p0 = (float)pos[r0 & (SEQ - 1)];
            float p1 = (float)pos[(r0 + 8) & (SEQ - 1)];
#pragma unroll
            for (int nt = 0; nt < 4; nt++) {
                int c = bn + warp_n * 32 + nt * 8 + 2 * tig;
                int d = c & (D_K - 1);   // even index within head
                float invf = expf(-lg * ((float)d / (float)D_K));
                float sn0, cs0, sn1, cs1;
                sincosf(p0 * invf, &sn0, &cs0);
                sincosf(p1 * invf, &sn1, &cs1);
                float v0 = acc[mt][nt][0], v1 = acc[mt][nt][1];
                float w0 = acc[mt][nt][2], w1 = acc[mt][nt][3];
                *(float2*)&C[(size_t)r0 * D_MODEL + c] =
                    make_float2(v0 * cs0 - v1 * sn0, v0 * sn0 + v1 * cs0);
                *(float2*)&C[(size_t)(r0 + 8) * D_MODEL + c] =
                    make_float2(w0 * cs1 - w1 * sn1, w0 * sn1 + w1 * cs1);
            }
        }
    } else {
#pragma unroll
        for (int mt = 0; mt < 4; mt++) {
            int r0 = bm + warp_m * 64 + mt * 16 + gid;
#pragma unroll
            for (int nt = 0; nt < 4; nt++) {
                int c = bn + warp_n * 32 + nt * 8 + 2 * tig;
                *(float2*)&C[(size_t)r0 * D_MODEL + c] =
                    make_float2(acc[mt][nt][0], acc[mt][nt][1]);
                *(float2*)&C[(size_t)(r0 + 8) * D_MODEL + c] =
                    make_float2(acc[mt][nt][2], acc[mt][nt][3]);
            }
        }
    }
}

// ---------------------------------------------------------------------------
// Flash attention with tf32 mma. Br=64, Bc=32, dk=64, causal.
// grid (SEQ/64, B*H), 256 threads = 8 warps.
// S buffer aliases K buffer (S stored [k][q] so softmax reads contiguously).
// ---------------------------------------------------------------------------
#define QS(d, q) Qsm[(d) * 72 + (q)]
#define KSM(d, k) KSbuf[(d) * 40 + (k)]
#define SS(k, q) KSbuf[(k) * 72 + (q)]
#define VS(k, d) Vsm[(k) * 72 + (d)]

__global__ __launch_bounds__(256, 2)
void attn_tf32(const float* __restrict__ Qg, const float* __restrict__ Kg,
               const float* __restrict__ Vg, float* __restrict__ Og)
{
    __shared__ float Qsm[64 * 72];   // Q^T: [d][q]
    __shared__ float KSbuf[2560];    // K^T: [d][k] (64x40) aliased with S: [k][q] (32x72)
    __shared__ float Vsm[32 * 72];   // V: [k][d]
    __shared__ float m_s[64], l_s[64], a_s[64];

    const int tid = threadIdx.x;
    const int warp = tid >> 5;
    const int lane = tid & 31;
    const int gid = lane >> 2;
    const int tig = lane & 3;
    const int wm = warp >> 1;        // 0..3 : q-tile (16 rows)
    const int wn = warp & 1;         // 0..1

    const int qt = blockIdx.x;
    const int bh = blockIdx.y;
    const int q0 = qt * 64;
    const size_t base = (size_t)(bh >> 4) * SEQ * D_MODEL + (size_t)(bh & 15) * D_K;

    // load Q tile (64x64) transposed, scaled by 1/sqrt(dk), tf32
    {
        int q = tid >> 2;
        int db = (tid & 3) * 4;
#pragma unroll
        for (int i = 0; i < 4; i++) {
            int d = db + i * 16;
            float4 v = *(const float4*)&Qg[base + (size_t)(q0 + q) * D_MODEL + d];
            QS(d + 0, q) = __uint_as_float(f2tf32(v.x * 0.125f));
            QS(d + 1, q) = __uint_as_float(f2tf32(v.y * 0.125f));
            QS(d + 2, q) = __uint_as_float(f2tf32(v.z * 0.125f));
            QS(d + 3, q) = __uint_as_float(f2tf32(v.w * 0.125f));
        }
    }
    if (tid < 64) { m_s[tid] = -1e30f; l_s[tid] = 0.0f; }

    float of[4][4];
#pragma unroll
    for (int i = 0; i < 4; i++)
#pragma unroll
        for (int j = 0; j < 4; j++) of[i][j] = 0.0f;

    const int qr = wm * 16 + gid;
    const int nkb = 2 * qt + 2;

    for (int kb = 0; kb < nkb; kb++) {
        const int k0 = kb * 32;
        {
            int k = tid >> 3;
            int db = (tid & 7) * 4;
#pragma unroll
            for (int i = 0; i < 2; i++) {
                int d = db + i * 32;
                float4 kv = *(const float4*)&Kg[base + (size_t)(k0 + k) * D_MODEL + d];
                float4 vv = *(const float4*)&Vg[base + (size_t)(k0 + k) * D_MODEL + d];
                KSM(d + 0, k) = __uint_as_float(f2tf32(kv.x));
                KSM(d + 1, k) = __uint_as_float(f2tf32(kv.y));
                KSM(d + 2, k) = __uint_as_float(f2tf32(kv.z));
                KSM(d + 3, k) = __uint_as_float(f2tf32(kv.w));
                VS(k, d + 0) = __uint_as_float(f2tf32(vv.x));
                VS(k, d + 1) = __uint_as_float(f2tf32(vv.y));
                VS(k, d + 2) = __uint_as_float(f2tf32(vv.z));
                VS(k, d + 3) = __uint_as_float(f2tf32(vv.w));
            }
        }
        __syncthreads();

        // S = Q K^T  (64x32): warp tile 16x16, 8 k-steps
        float sc[2][4];
#pragma unroll
        for (int nt = 0; nt < 2; nt++)
#pragma unroll
            for (int v = 0; v < 4; v++) sc[nt][v] = 0.0f;
#pragma unroll
        for (int ks = 0; ks < 64; ks += 8) {
            uint32_t a0 = __float_as_uint(QS(ks + tig, qr));
            uint32_t a1 = __float_as_uint(QS(ks + tig, qr + 8));
            uint32_t a2 = __float_as_uint(QS(ks + tig + 4, qr));
            uint32_t a3 = __float_as_uint(QS(ks + tig + 4, qr + 8));
#pragma unroll
            for (int nt = 0; nt < 2; nt++) {
                int kc = wn * 16 + nt * 8 + gid;
                uint32_t b0 = __float_as_uint(KSM(ks + tig, kc));
                uint32_t b1 = __float_as_uint(KSM(ks + tig + 4, kc));
                mma_tf32(sc[nt], a0, a1, a2, a3, b0, b1);
            }
        }
        __syncthreads();   // all warps done reading K before overwriting as S

#pragma unroll
        for (int nt = 0; nt < 2; nt++) {
            int kc = wn * 16 + nt * 8 + 2 * tig;
            SS(kc, qr) = sc[nt][0];
            SS(kc + 1, qr) = sc[nt][1];
            SS(kc, qr + 8) = sc[nt][2];
            SS(kc + 1, qr + 8) = sc[nt][3];
        }
        __syncthreads();

        if (tid < 64) {
            int q = tid;
            int qg = q0 + q;
            float mold = m_s[q];
            float mx = mold;
#pragma unroll
            for (int c = 0; c < 32; c++)
                if (k0 + c <= qg) mx = fmaxf(mx, SS(c, q));
            float al = __expf(mold - mx);
            float sum = 0.0f;
#pragma unroll
            for (int c = 0; c < 32; c++) {
                float p = (k0 + c <= qg) ? __expf(SS(c, q) - mx) : 0.0f;
                sum += p;
                SS(c, q) = __uint_as_float(f2tf32(p));
            }
            l_s[q] = l_s[q] * al + sum;
            m_s[q] = mx;
            a_s[q] = al;
        }
        __syncthreads();

        // O = O*alpha + P @ V  (64x64): warp tile 16x32, 4 k-steps
        {
            float al0 = a_s[qr];
            float al1 = a_s[qr + 8];
#pragma unroll
            for (int nt = 0; nt < 4; nt++) {
                of[nt][0] *= al0; of[nt][1] *= al0;
                of[nt][2] *= al1; of[nt][3] *= al1;
            }
#pragma unroll
            for (int ks = 0; ks < 32; ks += 8) {
                uint32_t a0 = __float_as_uint(SS(ks + tig, qr));
                uint32_t a1 = __float_as_uint(SS(ks + tig, qr + 8));
                uint32_t a2 = __float_as_uint(SS(ks + tig + 4, qr));
                uint32_t a3 = __float_as_uint(SS(ks + tig + 4, qr + 8));
#pragma unroll
                for (int nt = 0; nt < 4; nt++) {
                    int dc = wn * 32 + nt * 8 + gid;
                    uint32_t b0 = __float_as_uint(VS(ks + tig, dc));
                    uint32_t b1 = __float_as_uint(VS(ks + tig + 4, dc));
                    mma_tf32(of[nt], a0, a1, a2, a3, b0, b1);
                }
            }
        }
        __syncthreads();
    }

    {
        float inv0 = 1.0f / l_s[qr];
        float inv1 = 1.0f / l_s[qr + 8];
#pragma unroll
        for (int nt = 0; nt < 4; nt++) {
            int c = wn * 32 + nt * 8 + 2 * tig;
            *(float2*)&Og[base + (size_t)(q0 + qr) * D_MODEL + c] =
                make_float2(of[nt][0] * inv0, of[nt][1] * inv0);
            *(float2*)&Og[base + (size_t)(q0 + qr + 8) * D_MODEL + c] =
                make_float2(of[nt][2] * inv1, of[nt][3] * inv1);
        }
    }
}

// ---------------------------------------------------------------------------
extern "C" void kernel_launch(void* const* d_in, const int* in_sizes, int n_in,
                              void* d_out, int out_size)
{
    const float* x  = (const float*)d_in[0];
    const float* wq = (const float*)d_in[1];
    const float* wk = (const float*)d_in[2];
    const float* wv = (const float*)d_in[3];
    const float* wo = (const float*)d_in[4];
    const int* tok  = (const int*)d_in[5];
    float* out = (float*)d_out;

    float *qp, *kp, *vp, *op;
    cudaGetSymbolAddress((void**)&qp, g_q);
    cudaGetSymbolAddress((void**)&kp, g_k);
    cudaGetSymbolAddress((void**)&vp, g_v);
    cudaGetSymbolAddress((void**)&op, g_o);

    dim3 gg(D_MODEL / 128, MTOT / 128);   // (8, 64)
    gemm_tf32<<<gg, 256>>>(x, wq, qp, 1, tok);
    gemm_tf32<<<gg, 256>>>(x, wk, kp, 1, tok);
    gemm_tf32<<<gg, 256>>>(x, wv, vp, 0, nullptr);

    dim3 ga(SEQ / 64, BATCH * NUM_HEADS); // (32, 64)
    attn_tf32<<<ga, 256>>>(qp, kp, vp, op);

    gemm_tf32<<<gg, 256>>>(op, wo, out, 0, nullptr);
}

// round 3
// speedup vs baseline: 4.0749x; 1.3424x over previous
#include <cuda_runtime.h>
#include <cuda_bf16.h>
#include <math.h>
#include <stdint.h>

#define D_MODEL 1024
#define NUM_HEADS 16
#define SEQ 2048
#define BATCH 4
#define D_K 64
#define MTOT (BATCH * SEQ)   // 8192

// Scratch (static device globals; no runtime allocation allowed)
__device__ float g_q[MTOT * D_MODEL];
__device__ float g_k[MTOT * D_MODEL];
__device__ float g_v[MTOT * D_MODEL];
__device__ float g_o[MTOT * D_MODEL];

// ---------------------------------------------------------------------------
// helpers
// ---------------------------------------------------------------------------
__device__ __forceinline__ uint32_t f2tf32(float f) {
    uint32_t r;
    asm("cvt.rna.tf32.f32 %0, %1;" : "=r"(r) : "f"(f));
    return r;
}

__device__ __forceinline__ void mma_tf32(float c[4], uint32_t a0, uint32_t a1,
                                         uint32_t a2, uint32_t a3,
                                         uint32_t b0, uint32_t b1) {
    asm volatile(
        "mma.sync.aligned.m16n8k8.row.col.f32.tf32.tf32.f32 "
        "{%0,%1,%2,%3},{%4,%5,%6,%7},{%8,%9},{%0,%1,%2,%3};"
        : "+f"(c[0]), "+f"(c[1]), "+f"(c[2]), "+f"(c[3])
        : "r"(a0), "r"(a1), "r"(a2), "r"(a3), "r"(b0), "r"(b1));
}

// ---------------------------------------------------------------------------
// tf32 tensor-core GEMM, NT form: C[m,n] = sum_k A[m,k]*B[n,k]
// Block tile 128x128, BK=16, double-buffered smem, 256 threads = 8 warps,
// warp tile 64x32. rope != 0: RoPE on (even,odd) pairs per 64-wide head slice.
// ---------------------------------------------------------------------------
__global__ __launch_bounds__(256, 2)
void gemm_tf32(const float* __restrict__ A, const float* __restrict__ B,
               float* __restrict__ C, int rope, const int* __restrict__ pos)
{
    // K-major smem [k][m], row stride 136 (mod 32 == 8 -> conflict-free frags)
    __shared__ float As[2][16][136];
    __shared__ float Bs[2][16][136];

    const int tid = threadIdx.x;
    const int warp = tid >> 5;
    const int lane = tid & 31;
    const int gid = lane >> 2;       // 0..7
    const int tig = lane & 3;        // 0..3
    const int warp_m = warp >> 2;    // 0..1
    const int warp_n = warp & 3;     // 0..3

    const int bm = blockIdx.y * 128;
    const int bn = blockIdx.x * 128;

    const int lrow = tid >> 1;               // 0..127
    const int lcol8 = (tid & 1) * 8;         // 0 or 8

    float acc[4][4][4];
#pragma unroll
    for (int i = 0; i < 4; i++)
#pragma unroll
        for (int j = 0; j < 4; j++)
#pragma unroll
            for (int v = 0; v < 4; v++) acc[i][j][v] = 0.0f;

    const float* Arow = A + (size_t)(bm + lrow) * D_MODEL + lcol8;
    const float* Brow = B + (size_t)(bn + lrow) * D_MODEL + lcol8;

    float4 ra0, ra1, rb0, rb1;
    ra0 = *(const float4*)&Arow[0];
    ra1 = *(const float4*)&Arow[4];
    rb0 = *(const float4*)&Brow[0];
    rb1 = *(const float4*)&Brow[4];

    // store stage 0
    {
        As[0][lcol8 + 0][lrow] = __uint_as_float(f2tf32(ra0.x));
        As[0][lcol8 + 1][lrow] = __uint_as_float(f2tf32(ra0.y));
        As[0][lcol8 + 2][lrow] = __uint_as_float(f2tf32(ra0.z));
        As[0][lcol8 + 3][lrow] = __uint_as_float(f2tf32(ra0.w));
        As[0][lcol8 + 4][lrow] = __uint_as_float(f2tf32(ra1.x));
        As[0][lcol8 + 5][lrow] = __uint_as_float(f2tf32(ra1.y));
        As[0][lcol8 + 6][lrow] = __uint_as_float(f2tf32(ra1.z));
        As[0][lcol8 + 7][lrow] = __uint_as_float(f2tf32(ra1.w));
        Bs[0][lcol8 + 0][lrow] = __uint_as_float(f2tf32(rb0.x));
        Bs[0][lcol8 + 1][lrow] = __uint_as_float(f2tf32(rb0.y));
        Bs[0][lcol8 + 2][lrow] = __uint_as_float(f2tf32(rb0.z));
        Bs[0][lcol8 + 3][lrow] = __uint_as_float(f2tf32(rb0.w));
        Bs[0][lcol8 + 4][lrow] = __uint_as_float(f2tf32(rb1.x));
        Bs[0][lcol8 + 5][lrow] = __uint_as_float(f2tf32(rb1.y));
        Bs[0][lcol8 + 6][lrow] = __uint_as_float(f2tf32(rb1.z));
        Bs[0][lcol8 + 7][lrow] = __uint_as_float(f2tf32(rb1.w));
    }

    const int NKT = D_MODEL / 16;   // 64
    for (int kt = 0; kt < NKT; kt++) {
        __syncthreads();
        const int cur = kt & 1;
        const int nxt = cur ^ 1;

        if (kt + 1 < NKT) {
            const float* An = Arow + (kt + 1) * 16;
            const float* Bn = Brow + (kt + 1) * 16;
            ra0 = *(const float4*)&An[0];
            ra1 = *(const float4*)&An[4];
            rb0 = *(const float4*)&Bn[0];
            rb1 = *(const float4*)&Bn[4];
        }

#pragma unroll
        for (int ks = 0; ks < 16; ks += 8) {
            uint32_t af[4][4], bf[4][2];
#pragma unroll
            for (int mt = 0; mt < 4; mt++) {
                int r = warp_m * 64 + mt * 16 + gid;
                af[mt][0] = __float_as_uint(As[cur][ks + tig][r]);
                af[mt][1] = __float_as_uint(As[cur][ks + tig][r + 8]);
                af[mt][2] = __float_as_uint(As[cur][ks + tig + 4][r]);
                af[mt][3] = __float_as_uint(As[cur][ks + tig + 4][r + 8]);
            }
#pragma unroll
            for (int nt = 0; nt < 4; nt++) {
                int c = warp_n * 32 + nt * 8 + gid;
                bf[nt][0] = __float_as_uint(Bs[cur][ks + tig][c]);
                bf[nt][1] = __float_as_uint(Bs[cur][ks + tig + 4][c]);
            }
#pragma unroll
            for (int mt = 0; mt < 4; mt++)
#pragma unroll
                for (int nt = 0; nt < 4; nt++)
                    mma_tf32(acc[mt][nt], af[mt][0], af[mt][1], af[mt][2],
                             af[mt][3], bf[nt][0], bf[nt][1]);
        }

        if (kt + 1 < NKT) {
            As[nxt][lcol8 + 0][lrow] = __uint_as_float(f2tf32(ra0.x));
            As[nxt][lcol8 + 1][lrow] = __uint_as_float(f2tf32(ra0.y));
            As[nxt][lcol8 + 2][lrow] = __uint_as_float(f2tf32(ra0.z));
            As[nxt][lcol8 + 3][lrow] = __uint_as_float(f2tf32(ra0.w));
            As[nxt][lcol8 + 4][lrow] = __uint_as_float(f2tf32(ra1.x));
            As[nxt][lcol8 + 5][lrow] = __uint_as_float(f2tf32(ra1.y));
            As[nxt][lcol8 + 6][lrow] = __uint_as_float(f2tf32(ra1.z));
            As[nxt][lcol8 + 7][lrow] = __uint_as_float(f2tf32(ra1.w));
            Bs[nxt][lcol8 + 0][lrow] = __uint_as_float(f2tf32(rb0.x));
            Bs[nxt][lcol8 + 1][lrow] = __uint_as_float(f2tf32(rb0.y));
            Bs[nxt][lcol8 + 2][lrow] = __uint_as_float(f2tf32(rb0.z));
            Bs[nxt][lcol8 + 3][lrow] = __uint_as_float(f2tf32(rb0.w));
            Bs[nxt][lcol8 + 4][lrow] = __uint_as_float(f2tf32(rb1.x));
            Bs[nxt][lcol8 + 5][lrow] = __uint_as_float(f2tf32(rb1.y));
            Bs[nxt][lcol8 + 6][lrow] = __uint_as_float(f2tf32(rb1.z));
            Bs[nxt][lcol8 + 7][lrow] = __uint_as_float(f2tf32(rb1.w));
        }
    }

    if (rope) {
        const float lg = logf(10000.0f);
#pragma unroll
        for (int mt = 0; mt < 4; mt++) {
            int r0 = bm + warp_m * 64 + mt * 16 + gid;
            float p0 = (float)pos[r0 & (SEQ - 1)];
            float p1 = (float)pos[(r0 + 8) & (SEQ - 1)];
#pragma unroll
            for (int nt = 0; nt < 4; nt++) {
                int c = bn + warp_n * 32 + nt * 8 + 2 * tig;
                int d = c & (D_K - 1);   // even index within head
                float invf = expf(-lg * ((float)d / (float)D_K));
                float sn0, cs0, sn1, cs1;
                sincosf(p0 * invf, &sn0, &cs0);
                sincosf(p1 * invf, &sn1, &cs1);
                float v0 = acc[mt][nt][0], v1 = acc[mt][nt][1];
                float w0 = acc[mt][nt][2], w1 = acc[mt][nt][3];
                *(float2*)&C[(size_t)r0 * D_MODEL + c] =
                    make_float2(v0 * cs0 - v1 * sn0, v0 * sn0 + v1 * cs0);
                *(float2*)&C[(size_t)(r0 + 8) * D_MODEL + c] =
                    make_float2(w0 * cs1 - w1 * sn1, w0 * sn1 + w1 * cs1);
            }
        }
    } else {
#pragma unroll
        for (int mt = 0; mt < 4; mt++) {
            int r0 = bm + warp_m * 64 + mt * 16 + gid;
#pragma unroll
            for (int nt = 0; nt < 4; nt++) {
                int c = bn + warp_n * 32 + nt * 8 + 2 * tig;
                *(float2*)&C[(size_t)r0 * D_MODEL + c] =
                    make_float2(acc[mt][nt][0], acc[mt][nt][1]);
                *(float2*)&C[(size_t)(r0 + 8) * D_MODEL + c] =
                    make_float2(acc[mt][nt][2], acc[mt][nt][3]);
            }
        }
    }
}

// ---------------------------------------------------------------------------
// Flash attention, FA2-style. Br=128, Bc=32, dk=64, causal.
// 8 warps, each warp owns 16 q rows. Q fragments in registers.
// K,V stored NATURAL [k][d] (B-fragment indexing is [n][k] = natural K).
// Softmax fully in registers with quad shfl reductions; P via per-warp smem.
// ---------------------------------------------------------------------------
__global__ __launch_bounds__(256, 2)
void attn_tf32(const float* __restrict__ Qg, const float* __restrict__ Kg,
               const float* __restrict__ Vg, float* __restrict__ Og)
{
    __shared__ float Ks[32][68];       // natural [k][d]
    __shared__ float Vs[32][72];       // natural [k][d]
    __shared__ float Ps[8][16][36];    // per-warp P tile [q16][k32]

    const int tid = threadIdx.x;
    const int warp = tid >> 5;
    const int lane = tid & 31;
    const int gid = lane >> 2;   // 0..7
    const int tig = lane & 3;    // 0..3

    const int qt = (int)gridDim.x - 1 - (int)blockIdx.x;  // heavy blocks first
    const int bh = blockIdx.y;
    const int q0 = qt * 128;
    const size_t base = (size_t)(bh >> 4) * SEQ * D_MODEL + (size_t)(bh & 15) * D_K;

    const int qw = q0 + warp * 16;          // warp's first q row
    const int rowmax = qw + 15;

    // Q fragments (scaled by 1/sqrt(dk), tf32), loaded once from gmem
    uint32_t qa[8][4];
    {
        const float* Qr0 = Qg + base + (size_t)(qw + gid) * D_MODEL;
        const float* Qr1 = Qr0 + 8 * D_MODEL;
#pragma unroll
        for (int ks = 0; ks < 8; ks++) {
            qa[ks][0] = f2tf32(Qr0[ks * 8 + tig] * 0.125f);
            qa[ks][1] = f2tf32(Qr1[ks * 8 + tig] * 0.125f);
            qa[ks][2] = f2tf32(Qr0[ks * 8 + tig + 4] * 0.125f);
            qa[ks][3] = f2tf32(Qr1[ks * 8 + tig + 4] * 0.125f);
        }
    }

    float of[8][4];
#pragma unroll
    for (int i = 0; i < 8; i++)
#pragma unroll
        for (int j = 0; j < 4; j++) of[i][j] = 0.0f;
    float m0 = -1e30f, m1 = -1e30f, l0 = 0.0f, l1 = 0.0f;

    const int nkb = (q0 + 128) / 32;   // 4*qt + 4

    for (int kb = 0; kb < nkb; kb++) {
        const int k0 = kb * 32;
        // load K,V tiles (32 x 64 each), tf32, natural layout
#pragma unroll
        for (int i = 0; i < 2; i++) {
            int idx = tid + i * 256;        // 0..511
            int k = idx >> 4;
            int d = (idx & 15) * 4;
            float4 kv = *(const float4*)&Kg[base + (size_t)(k0 + k) * D_MODEL + d];
            float4 vv = *(const float4*)&Vg[base + (size_t)(k0 + k) * D_MODEL + d];
            Ks[k][d + 0] = __uint_as_float(f2tf32(kv.x));
            Ks[k][d + 1] = __uint_as_float(f2tf32(kv.y));
            Ks[k][d + 2] = __uint_as_float(f2tf32(kv.z));
            Ks[k][d + 3] = __uint_as_float(f2tf32(kv.w));
            Vs[k][d + 0] = __uint_as_float(f2tf32(vv.x));
            Vs[k][d + 1] = __uint_as_float(f2tf32(vv.y));
            Vs[k][d + 2] = __uint_as_float(f2tf32(vv.z));
            Vs[k][d + 3] = __uint_as_float(f2tf32(vv.w));
        }
        __syncthreads();

        if (k0 <= rowmax) {
            // S = Q K^T : warp tile 16x32 = 4 n-tiles, 8 k-steps
            float sc[4][4];
#pragma unroll
            for (int nt = 0; nt < 4; nt++)
#pragma unroll
                for (int v = 0; v < 4; v++) sc[nt][v] = 0.0f;
#pragma unroll
            for (int ks = 0; ks < 8; ks++) {
#pragma unroll
                for (int nt = 0; nt < 4; nt++) {
                    int kc = nt * 8 + gid;
                    uint32_t b0 = __float_as_uint(Ks[kc][ks * 8 + tig]);
                    uint32_t b1 = __float_as_uint(Ks[kc][ks * 8 + tig + 4]);
                    mma_tf32(sc[nt], qa[ks][0], qa[ks][1], qa[ks][2], qa[ks][3],
                             b0, b1);
                }
            }

            // causal mask (only for diagonal-overlapping blocks)
            if (k0 + 31 > qw) {
                int r0g = qw + gid;
                int r1g = r0g + 8;
#pragma unroll
                for (int nt = 0; nt < 4; nt++) {
                    int c = k0 + nt * 8 + 2 * tig;
                    if (c > r0g)     sc[nt][0] = -1e30f;
                    if (c + 1 > r0g) sc[nt][1] = -1e30f;
                    if (c > r1g)     sc[nt][2] = -1e30f;
                    if (c + 1 > r1g) sc[nt][3] = -1e30f;
                }
            }

            // row max over 32 cols: local over nt then quad shfl
            float mx0 = sc[0][0], mx1 = sc[0][2];
#pragma unroll
            for (int nt = 0; nt < 4; nt++) {
                mx0 = fmaxf(mx0, fmaxf(sc[nt][0], sc[nt][1]));
                mx1 = fmaxf(mx1, fmaxf(sc[nt][2], sc[nt][3]));
            }
            mx0 = fmaxf(mx0, __shfl_xor_sync(0xffffffffu, mx0, 1));
            mx0 = fmaxf(mx0, __shfl_xor_sync(0xffffffffu, mx0, 2));
            mx1 = fmaxf(mx1, __shfl_xor_sync(0xffffffffu, mx1, 1));
            mx1 = fmaxf(mx1, __shfl_xor_sync(0xffffffffu, mx1, 2));

            float mn0 = fmaxf(m0, mx0);
            float mn1 = fmaxf(m1, mx1);
            float al0 = __expf(m0 - mn0);
            float al1 = __expf(m1 - mn1);
            m0 = mn0; m1 = mn1;

            float sum0 = 0.0f, sum1 = 0.0f;
#pragma unroll
            for (int nt = 0; nt < 4; nt++) {
                float p0 = __expf(sc[nt][0] - mn0);
                float p1 = __expf(sc[nt][1] - mn0);
                float p2 = __expf(sc[nt][2] - mn1);
                float p3 = __expf(sc[nt][3] - mn1);
                sum0 += p0 + p1;
                sum1 += p2 + p3;
                sc[nt][0] = __uint_as_float(f2tf32(p0));
                sc[nt][1] = __uint_as_float(f2tf32(p1));
                sc[nt][2] = __uint_as_float(f2tf32(p2));
                sc[nt][3] = __uint_as_float(f2tf32(p3));
            }
            sum0 += __shfl_xor_sync(0xffffffffu, sum0, 1);
            sum0 += __shfl_xor_sync(0xffffffffu, sum0, 2);
            sum1 += __shfl_xor_sync(0xffffffffu, sum1, 1);
            sum1 += __shfl_xor_sync(0xffffffffu, sum1, 2);
            l0 = l0 * al0 + sum0;
            l1 = l1 * al1 + sum1;

            // rescale O
#pragma unroll
            for (int nt = 0; nt < 8; nt++) {
                of[nt][0] *= al0; of[nt][1] *= al0;
                of[nt][2] *= al1; of[nt][3] *= al1;
            }

            // write P to per-warp smem (A-fragment layout source)
#pragma unroll
            for (int nt = 0; nt < 4; nt++) {
                *(float2*)&Ps[warp][gid][nt * 8 + 2 * tig] =
                    make_float2(sc[nt][0], sc[nt][1]);
                *(float2*)&Ps[warp][gid + 8][nt * 8 + 2 * tig] =
                    make_float2(sc[nt][2], sc[nt][3]);
            }
            __syncwarp();

            // O += P @ V : 4 k-steps x 8 n-tiles
#pragma unroll
            for (int ks = 0; ks < 4; ks++) {
                uint32_t a0 = __float_as_uint(Ps[warp][gid][ks * 8 + tig]);
                uint32_t a1 = __float_as_uint(Ps[warp][gid + 8][ks * 8 + tig]);
                uint32_t a2 = __float_as_uint(Ps[warp][gid][ks * 8 + tig + 4]);
                uint32_t a3 = __float_as_uint(Ps[warp][gid + 8][ks * 8 + tig + 4]);
#pragma unroll
                for (int nt = 0; nt < 8; nt++) {
                    int dc = nt * 8 + gid;
                    uint32_t b0 = __float_as_uint(Vs[ks * 8 + tig][dc]);
                    uint32_t b1 = __float_as_uint(Vs[ks * 8 + tig + 4][dc]);
                    mma_tf32(of[nt], a0, a1, a2, a3, b0, b1);
                }
            }
            __syncwarp();
        }
        __syncthreads();
    }

    // normalize + write (rows always have >=1 unmasked col -> l > 0)
    {
        float inv0 = 1.0f / l0;
        float inv1 = 1.0f / l1;
        float* O0 = Og + base + (size_t)(qw + gid) * D_MODEL;
        float* O1 = O0 + 8 * D_MODEL;
#pragma unroll
        for (int nt = 0; nt < 8; nt++) {
            int c = nt * 8 + 2 * tig;
            *(float2*)&O0[c] = make_float2(of[nt][0] * inv0, of[nt][1] * inv0);
            *(float2*)&O1[c] = make_float2(of[nt][2] * inv1, of[nt][3] * inv1);
        }
    }
}

// ---------------------------------------------------------------------------
extern "C" void kernel_launch(void* const* d_in, const int* in_sizes, int n_in,
                              void* d_out, int out_size)
{
    const float* x  = (const float*)d_in[0];
    const float* wq = (const float*)d_in[1];
    const float* wk = (const float*)d_in[2];
    const float* wv = (const float*)d_in[3];
    const float* wo = (const float*)d_in[4];
    const int* tok  = (const int*)d_in[5];
    float* out = (float*)d_out;

    float *qp, *kp, *vp, *op;
    cudaGetSymbolAddress((void**)&qp, g_q);
    cudaGetSymbolAddress((void**)&kp, g_k);
    cudaGetSymbolAddress((void**)&vp, g_v);
    cudaGetSymbolAddress((void**)&op, g_o);

    dim3 gg(D_MODEL / 128, MTOT / 128);   // (8, 64)
    gemm_tf32<<<gg, 256>>>(x, wq, qp, 1, tok);
    gemm_tf32<<<gg, 256>>>(x, wk, kp, 1, tok);
    gemm_tf32<<<gg, 256>>>(x, wv, vp, 0, nullptr);

    dim3 ga(SEQ / 128, BATCH * NUM_HEADS); // (16, 64)
    attn_tf32<<<ga, 256>>>(qp, kp, vp, op);

    gemm_tf32<<<gg, 256>>>(op, wo, out, 0, nullptr);
}